// round 5
// baseline (speedup 1.0000x reference)
#include <cuda_runtime.h>
#include <math.h>

// ---------------------------------------------------------------------------
// Problem constants (compile-time fast path; dims derived at runtime where cheap)
// ---------------------------------------------------------------------------
#define EMBC 128                 // F_IN == EMB == HID == 128
#define RELC 8                   // N_REL
#define NCC  ((RELC + 1) * EMBC) // 1152 : 8 relation blocks + root block
#define MAXN 50176               // max nodes (padded to /128)
#define MAXG 256                 // max graphs

// ---------------------------------------------------------------------------
// Scratch (device globals: no allocation allowed in kernel_launch)
// ---------------------------------------------------------------------------
__device__ float g_hW[(size_t)MAXN * NCC];       // [N, 9, 128] per-node per-rel (+root) transform
__device__ float g_h[(size_t)MAXN * EMBC];       // hidden after layer 1
__device__ float g_Wcat[2][NCC * EMBC];          // repacked [F, (R+1)*O] for each layer
__device__ float g_msg[MAXG * EMBC];             // message_repr per graph
__device__ int   g_flags[4];                     // [0]=edge_index is int64, [1]=edge_type is int64

// ---------------------------------------------------------------------------
// f32x2 helpers (FFMA2 is PTX-only; 2x issue rate vs 3-reg FFMA on sm_103a)
// ---------------------------------------------------------------------------
__device__ __forceinline__ unsigned long long pack2(float lo, float hi) {
    unsigned long long d;
    asm("mov.b64 %0, {%1, %2};" : "=l"(d)
        : "r"(__float_as_uint(lo)), "r"(__float_as_uint(hi)));
    return d;
}
__device__ __forceinline__ void unpack2(unsigned long long v, float& lo, float& hi) {
    unsigned int l, h;
    asm("mov.b64 {%0, %1}, %2;" : "=r"(l), "=r"(h) : "l"(v));
    lo = __uint_as_float(l); hi = __uint_as_float(h);
}
__device__ __forceinline__ unsigned long long fma2(unsigned long long a,
                                                   unsigned long long b,
                                                   unsigned long long c) {
    unsigned long long d;
    asm("fma.rn.f32x2 %0, %1, %2, %3;" : "=l"(d) : "l"(a), "l"(b), "l"(c));
    return d;
}

// ---------------------------------------------------------------------------
// int32 vs int64 index detection: for int64 (values >= 0, < 2^31) every odd
// 32-bit word is 0; for int32 the odd words are real elements (OR != 0 w.p. 1).
// ---------------------------------------------------------------------------
__global__ void detect_kernel(const unsigned int* ei, const unsigned int* et) {
    __shared__ unsigned int s[2];
    if (threadIdx.x < 2) s[threadIdx.x] = 0u;
    __syncthreads();
    unsigned int a = 0u, b = 0u;
    for (int i = threadIdx.x; i < 1024; i += blockDim.x) {
        a |= ei[2 * i + 1];
        b |= et[2 * i + 1];
    }
    atomicOr(&s[0], a);
    atomicOr(&s[1], b);
    __syncthreads();
    if (threadIdx.x == 0) {
        g_flags[0] = (s[0] == 0u);
        g_flags[1] = (s[1] == 0u);
    }
}

__device__ __forceinline__ long long ldidx(const void* p, size_t i, int is64) {
    return is64 ? ((const long long*)p)[i] : (long long)((const int*)p)[i];
}

// ---------------------------------------------------------------------------
// Repack W[r,f,o] (+ root as r=R) into Wcat[f, r*O+o] for both layers
// ---------------------------------------------------------------------------
__global__ void repack_kernel(const float* __restrict__ W1, const float* __restrict__ r1,
                              const float* __restrict__ W2, const float* __restrict__ r2) {
    int i = blockIdx.x * blockDim.x + threadIdx.x;
    if (i >= EMBC * NCC) return;
    int f = i / NCC;
    int c = i - f * NCC;
    int r = c >> 7;          // c / 128
    int o = c & 127;
    float v1 = (r < RELC) ? W1[((size_t)r * EMBC + f) * EMBC + o] : r1[(size_t)f * EMBC + o];
    float v2 = (r < RELC) ? W2[((size_t)r * EMBC + f) * EMBC + o] : r2[(size_t)f * EMBC + o];
    g_Wcat[0][i] = v1;
    g_Wcat[1][i] = v2;
}

// ---------------------------------------------------------------------------
// message_repr: one block (128 threads) per graph
// ---------------------------------------------------------------------------
__global__ void msg_kernel(const float* __restrict__ message,
                           const float* __restrict__ embed,
                           const float* __restrict__ cw, const float* __restrict__ cb,
                           const float* __restrict__ mw, const float* __restrict__ mb,
                           int vocab) {
    __shared__ float s[2 * EMBC];
    int g = blockIdx.x, o = threadIdx.x;
    int tok = (int)message[(size_t)g * 2];
    float cont = message[(size_t)g * 2 + 1];
    if (tok < 0) tok = 0;
    if (tok >= vocab) tok = vocab - 1;
    s[o]        = embed[(size_t)tok * EMBC + o];
    s[EMBC + o] = fmaxf(cont * cw[o] + cb[o], 0.0f);
    __syncthreads();
    float acc = mb[o];
#pragma unroll 8
    for (int j = 0; j < 2 * EMBC; j++) acc += s[j] * mw[(size_t)j * EMBC + o];
    g_msg[(size_t)g * EMBC + o] = fmaxf(acc, 0.0f);
}

// ---------------------------------------------------------------------------
// GEMM: C[M,1152] = A[M,128] @ Wcat[128,1152]; CTA tile 128x128, full K in smem.
// 256 threads, 8x8 outputs/thread via f32x2 (pairs of interleaved columns).
// Column map c = tx + 16*j and A stride 129 -> conflict-free broadcast LDS.
// ---------------------------------------------------------------------------
__global__ void __launch_bounds__(256, 1)
gemm_kernel(const float* __restrict__ Aext, int useH, int M, int layer) {
    const float* __restrict__ A = useH ? (const float*)g_h : Aext;
    extern __shared__ float sm[];
    float* As = sm;                  // [128][129]
    float* Bs = sm + 128 * 129;      // [128][128]
    const int tid = threadIdx.x;
    const int m0 = blockIdx.x * 128;
    const int cb = blockIdx.y * 128;
    const float* __restrict__ Wc = g_Wcat[layer];

    // load A tile (guarded, zero-fill tail rows)
    for (int idx = tid * 4; idx < 128 * 128; idx += 256 * 4) {
        int row = idx >> 7, k = idx & 127;
        float4 v = make_float4(0.f, 0.f, 0.f, 0.f);
        int gr = m0 + row;
        if (gr < M) v = *reinterpret_cast<const float4*>(&A[(size_t)gr * EMBC + k]);
        float* dst = &As[row * 129 + k];
        dst[0] = v.x; dst[1] = v.y; dst[2] = v.z; dst[3] = v.w;
    }
    // load B tile
    for (int idx = tid * 4; idx < 128 * 128; idx += 256 * 4) {
        int k = idx >> 7, c = idx & 127;
        *reinterpret_cast<float4*>(&Bs[k * 128 + c]) =
            *reinterpret_cast<const float4*>(&Wc[(size_t)k * NCC + cb + c]);
    }
    __syncthreads();

    const int tx = tid & 15, ty = tid >> 4;
    unsigned long long acc[8][4];
#pragma unroll
    for (int i = 0; i < 8; i++)
#pragma unroll
        for (int j = 0; j < 4; j++) acc[i][j] = 0ull;

#pragma unroll 4
    for (int k = 0; k < 128; k++) {
        unsigned long long a2[8];
#pragma unroll
        for (int i = 0; i < 8; i++) {
            float a = As[(ty * 8 + i) * 129 + k];
            a2[i] = pack2(a, a);
        }
        float b[8];
#pragma unroll
        for (int j = 0; j < 8; j++) b[j] = Bs[k * 128 + tx + 16 * j];
        unsigned long long b2[4];
#pragma unroll
        for (int j = 0; j < 4; j++) b2[j] = pack2(b[2 * j], b[2 * j + 1]);
#pragma unroll
        for (int i = 0; i < 8; i++)
#pragma unroll
            for (int j = 0; j < 4; j++) acc[i][j] = fma2(a2[i], b2[j], acc[i][j]);
    }

#pragma unroll
    for (int i = 0; i < 8; i++) {
        int gr = m0 + ty * 8 + i;
        if (gr >= M) continue;
        float* outr = &g_hW[(size_t)gr * NCC + cb];
#pragma unroll
        for (int j = 0; j < 4; j++) {
            float lo, hi;
            unpack2(acc[i][j], lo, hi);
            outr[tx + 32 * j]      = lo;   // col pair (tx+32j, tx+32j+16)
            outr[tx + 32 * j + 16] = hi;
        }
    }
}

// ---------------------------------------------------------------------------
// Per-graph aggregation: one CTA per graph. Edges of graph g occupy
// [g*epg, (g+1)*epg); node ids occupy [g*npg, (g+1)*npg). Mean over (dst,rel)
// via smem counts; agg accumulated in smem (no global atomics).
// layer2 fuses the dot-score against message_repr and writes logits directly.
// ---------------------------------------------------------------------------
__global__ void __launch_bounds__(256)
agg_kernel(const void* __restrict__ ei, const void* __restrict__ et,
           const float* __restrict__ bias, float* __restrict__ outp,
           int layer2, int n_graphs, int npg, int epg, int E, int max_nodes) {
    extern __shared__ float sm[];
    float* agg  = sm;                           // npg * EMBC
    int*   cnt  = (int*)(sm + (size_t)npg * EMBC);  // npg * RELC
    float* msgs = (float*)(cnt + (size_t)npg * RELC); // EMBC (layer2 only)

    const int g   = blockIdx.x;
    const int bn  = g * npg;
    const int eb  = g * epg;
    const int tid = threadIdx.x;
    const int ei64 = g_flags[0], et64 = g_flags[1];

    for (int i = tid; i < npg * EMBC; i += blockDim.x) agg[i] = 0.0f;
    for (int i = tid; i < npg * RELC; i += blockDim.x) cnt[i] = 0;
    if (layer2)
        for (int i = tid; i < EMBC; i += blockDim.x) msgs[i] = g_msg[(size_t)g * EMBC + i];
    __syncthreads();

    // phase 1: counts per (dst, rel)
    for (int e = eb + tid; e < eb + epg; e += blockDim.x) {
        int dst = (int)ldidx(ei, (size_t)E + e, ei64);
        int t   = (int)ldidx(et, (size_t)e, et64);
        atomicAdd(&cnt[(dst - bn) * RELC + t], 1);
    }
    __syncthreads();

    // phase 2: warp per edge, gather hW row, scaled smem accumulate
    const int warp = tid >> 5, lane = tid & 31;
    const int nw = blockDim.x >> 5;
    for (int e = eb + warp; e < eb + epg; e += nw) {
        int src = (int)ldidx(ei, (size_t)e, ei64);
        int dst = (int)ldidx(ei, (size_t)E + e, ei64);
        int t   = (int)ldidx(et, (size_t)e, et64);
        int dl  = dst - bn;
        float norm = 1.0f / (float)cnt[dl * RELC + t];
        const float4 v = *reinterpret_cast<const float4*>(
            &g_hW[(size_t)src * NCC + t * EMBC + lane * 4]);
        float* ar = &agg[dl * EMBC + lane * 4];
        atomicAdd(ar + 0, v.x * norm);
        atomicAdd(ar + 1, v.y * norm);
        atomicAdd(ar + 2, v.z * norm);
        atomicAdd(ar + 3, v.w * norm);
    }
    __syncthreads();

    if (!layer2) {
        // h = relu(agg + x@root + b)   (root term is hW block r=RELC)
        for (int i = tid; i < npg * EMBC; i += blockDim.x) {
            int m = i >> 7, o = i & 127;
            float v = agg[i] + g_hW[(size_t)(bn + m) * NCC + RELC * EMBC + o] + bias[o];
            g_h[(size_t)(bn + m) * EMBC + o] = fmaxf(v, 0.0f);
        }
    } else {
        // logits[g, m] = dot(node_emb[bn+m], message_repr[g])
        for (int m = warp; m < npg; m += nw) {
            float p = 0.0f;
            for (int o = lane; o < EMBC; o += 32) {
                float v = agg[m * EMBC + o] +
                          g_hW[(size_t)(bn + m) * NCC + RELC * EMBC + o] + bias[o];
                p += v * msgs[o];
            }
#pragma unroll
            for (int s = 16; s > 0; s >>= 1) p += __shfl_down_sync(0xffffffffu, p, s);
            if (lane == 0) outp[(size_t)g * max_nodes + m] = p;
        }
        // padded slots (npg..max_nodes) -> -inf
        for (int p2 = npg + tid; p2 < max_nodes; p2 += blockDim.x)
            outp[(size_t)g * max_nodes + p2] = -INFINITY;
    }
}

// ---------------------------------------------------------------------------
// Launch
// Inputs (metadata order): 0 message, 1 x, 2 edge_index, 3 edge_type, 4 batch,
// 5 max_nodes, 6 W1, 7 root1, 8 b1, 9 W2, 10 root2, 11 b2, 12 embed_table,
// 13 cont_w, 14 cont_b, 15 msg_w, 16 msg_b
// ---------------------------------------------------------------------------
extern "C" void kernel_launch(void* const* d_in, const int* in_sizes, int n_in,
                              void* d_out, int out_size) {
    const float* message = (const float*)d_in[0];
    const float* x       = (const float*)d_in[1];
    const void*  ei      = d_in[2];
    const void*  et      = d_in[3];
    const float* W1      = (const float*)d_in[6];
    const float* r1      = (const float*)d_in[7];
    const float* b1      = (const float*)d_in[8];
    const float* W2      = (const float*)d_in[9];
    const float* r2      = (const float*)d_in[10];
    const float* b2      = (const float*)d_in[11];
    const float* emb     = (const float*)d_in[12];
    const float* cw      = (const float*)d_in[13];
    const float* cbv     = (const float*)d_in[14];
    const float* mw      = (const float*)d_in[15];
    const float* mb      = (const float*)d_in[16];

    const int n_graphs  = in_sizes[0] / 2;
    const int n_nodes   = in_sizes[4];
    const int E         = in_sizes[3];
    const int vocab     = in_sizes[12] / EMBC;
    const int npg       = n_nodes / n_graphs;
    const int epg       = E / n_graphs;
    const int max_nodes = out_size / n_graphs;
    float* outp = (float*)d_out;

    const size_t gemm_sm = (size_t)(128 * 129 + 128 * 128) * sizeof(float); // 131584 B
    const size_t agg_sm  = (size_t)npg * EMBC * 4 + (size_t)npg * RELC * 4 + EMBC * 4;
    cudaFuncSetAttribute(gemm_kernel, cudaFuncAttributeMaxDynamicSharedMemorySize, (int)gemm_sm);
    cudaFuncSetAttribute(agg_kernel,  cudaFuncAttributeMaxDynamicSharedMemorySize, (int)agg_sm);

    detect_kernel<<<1, 256>>>((const unsigned int*)ei, (const unsigned int*)et);
    repack_kernel<<<(EMBC * NCC + 255) / 256, 256>>>(W1, r1, W2, r2);
    msg_kernel<<<n_graphs, EMBC>>>(message, emb, cw, cbv, mw, mb, vocab);

    dim3 ggrid((n_nodes + 127) / 128, NCC / 128);

    // layer 1
    gemm_kernel<<<ggrid, 256, gemm_sm>>>(x, 0, n_nodes, 0);
    agg_kernel<<<n_graphs, 256, agg_sm>>>(ei, et, b1, outp, 0, n_graphs, npg, epg, E, max_nodes);
    // layer 2 (+ fused scoring into logits)
    gemm_kernel<<<ggrid, 256, gemm_sm>>>(nullptr, 1, n_nodes, 1);
    agg_kernel<<<n_graphs, 256, agg_sm>>>(ei, et, b2, outp, 1, n_graphs, npg, epg, E, max_nodes);
}

// round 11
// speedup vs baseline: 2.3863x; 2.3863x over previous
#include <cuda_runtime.h>
#include <cuda_bf16.h>
#include <stdint.h>
#include <math.h>

typedef unsigned int u32;
typedef unsigned long long u64;

// ---------------------------------------------------------------------------
// Problem constants
// ---------------------------------------------------------------------------
#define EMBC 128                  // F_IN == EMB == HID == 128
#define RELC 8                    // N_REL
#define KTOT ((RELC + 1) * EMBC)  // 1152 : 8 rel-agg blocks + h-copy (root) block
#define KC   32                   // K per smem tile
#define NKT  (KTOT / KC)          // 36 tiles
#define MAXN 50176
#define MAXG 256

// ---------------------------------------------------------------------------
// Scratch (device globals: no allocation allowed)
// ---------------------------------------------------------------------------
__device__ float g_agg[(size_t)MAXN * KTOT];   // [N,1152] aggregated features (+h copy)
__device__ float g_h[(size_t)MAXN * EMBC];     // layer output (h1, then node_emb)
__device__ float g_msg[MAXG * EMBC];           // message_repr per graph
__device__ u32   g_Wt[2 * NKT * 2 * KC * EMBC]; // tf32 B tiles [layer][kt][hi/lo][32][128]
__device__ int   g_flags[4];                   // [0]=edge_index int64, [1]=edge_type int64

// ---------------------------------------------------------------------------
// PTX helpers (plain sm_103 features only: cp.async + mma.sync)
// ---------------------------------------------------------------------------
__device__ __forceinline__ u32 smem_to_u32(const void* p) {
    u32 a;
    asm("{ .reg .u64 t; cvta.to.shared.u64 t, %1; cvt.u32.u64 %0, t; }" : "=r"(a) : "l"(p));
    return a;
}
__device__ __forceinline__ void cp16(u32 dst, const void* src) {
    asm volatile("cp.async.cg.shared.global [%0], [%1], 16;" :: "r"(dst), "l"(src));
}
#define CP_COMMIT() asm volatile("cp.async.commit_group;" ::: "memory")
#define CP_WAIT(n)  asm volatile("cp.async.wait_group %0;" :: "n"(n) : "memory")

__device__ __forceinline__ u32 f2tf(float f) {
    u32 r;
    asm("cvt.rna.tf32.f32 %0, %1;" : "=r"(r) : "f"(f));
    return r;
}
__device__ __forceinline__ void mma_tf32(float& c0, float& c1, float& c2, float& c3,
                                         u32 a0, u32 a1, u32 a2, u32 a3, u32 b0, u32 b1) {
    asm("mma.sync.aligned.m16n8k8.row.col.f32.tf32.tf32.f32 "
        "{%0,%1,%2,%3}, {%4,%5,%6,%7}, {%8,%9}, {%0,%1,%2,%3};"
        : "+f"(c0), "+f"(c1), "+f"(c2), "+f"(c3)
        : "r"(a0), "r"(a1), "r"(a2), "r"(a3), "r"(b0), "r"(b1));
}

// ---------------------------------------------------------------------------
// index width helpers
// ---------------------------------------------------------------------------
__device__ __forceinline__ long long ldidx(const void* p, size_t i, int is64) {
    return is64 ? ((const long long*)p)[i] : (long long)((const int*)p)[i];
}

__global__ void detect_kernel(const u32* ei, const u32* et) {
    __shared__ u32 s[2];
    if (threadIdx.x < 2) s[threadIdx.x] = 0u;
    __syncthreads();
    u32 a = 0u, b = 0u;
    for (int i = threadIdx.x; i < 1024; i += blockDim.x) { a |= ei[2 * i + 1]; b |= et[2 * i + 1]; }
    atomicOr(&s[0], a); atomicOr(&s[1], b);
    __syncthreads();
    if (threadIdx.x == 0) { g_flags[0] = (s[0] == 0u); g_flags[1] = (s[1] == 0u); }
}

// ---------------------------------------------------------------------------
// Repack weights into tf32 hi/lo tiles: B[k=r*128+f][n=o] = W_r[f][o], root r=8.
// g_Wt layout: [layer][kt][s(hi/lo)][kk(32)][n(128)] u32 tf32.
// ---------------------------------------------------------------------------
__global__ void repack_kernel(const float* __restrict__ W1, const float* __restrict__ r1,
                              const float* __restrict__ W2, const float* __restrict__ r2) {
    int i = blockIdx.x * blockDim.x + threadIdx.x;
    if (i >= 2 * KTOT * EMBC) return;
    int layer = i / (KTOT * EMBC);
    int rem = i - layer * (KTOT * EMBC);
    int k = rem / EMBC;
    int n = rem - k * EMBC;
    int r = k >> 7, f = k & 127;
    const float* W = layer ? W2 : W1;
    const float* rt = layer ? r2 : r1;
    float v = (r < RELC) ? W[((size_t)r * EMBC + f) * EMBC + n] : rt[(size_t)f * EMBC + n];
    u32 hi = f2tf(v);
    u32 lo = f2tf(v - __uint_as_float(hi));
    int kt = k / KC, kk = k - kt * KC;
    size_t base = (((size_t)layer * NKT + kt) * 2) * (KC * EMBC) + (size_t)kk * EMBC + n;
    g_Wt[base] = hi;
    g_Wt[base + KC * EMBC] = lo;
}

// ---------------------------------------------------------------------------
// message_repr: one block (128 threads) per graph
// ---------------------------------------------------------------------------
__global__ void msg_kernel(const float* __restrict__ message, const float* __restrict__ embed,
                           const float* __restrict__ cw, const float* __restrict__ cb,
                           const float* __restrict__ mw, const float* __restrict__ mb, int vocab) {
    __shared__ float s[2 * EMBC];
    int g = blockIdx.x, o = threadIdx.x;
    int tok = (int)message[(size_t)g * 2];
    float cont = message[(size_t)g * 2 + 1];
    if (tok < 0) tok = 0;
    if (tok >= vocab) tok = vocab - 1;
    s[o] = embed[(size_t)tok * EMBC + o];
    s[EMBC + o] = fmaxf(cont * cw[o] + cb[o], 0.0f);
    __syncthreads();
    float acc = mb[o];
#pragma unroll 8
    for (int j = 0; j < 2 * EMBC; j++) acc += s[j] * mw[(size_t)j * EMBC + o];
    g_msg[(size_t)g * EMBC + o] = fmaxf(acc, 0.0f);
}

// ---------------------------------------------------------------------------
// Aggregation (per-graph CTA, CSR-in-smem, register accumulation, no hot-phase
// smem atomics). Writes g_agg[n,1152]: blocks r=0..7 bucket means of hin,
// block 8 = copy of hin (root path). useH selects g_h as input (device symbol
// cannot be passed from host).
// ---------------------------------------------------------------------------
__global__ void __launch_bounds__(256)
agg_kernel(const float* __restrict__ xext, int useH, const void* __restrict__ ei,
           const void* __restrict__ et, int npg, int epg, int E) {
    const float* __restrict__ hin = useH ? (const float*)g_h : xext;
    extern __shared__ int smi[];
    const int nb = npg * RELC;
    int* cnt    = smi;             // nb
    int* offs   = cnt + nb;        // nb
    int* cursor = offs + nb;       // nb
    int* ebuck  = cursor + nb;     // epg
    int* esrc   = ebuck + epg;     // epg
    __shared__ int ws[8];

    const int g = blockIdx.x, bn = g * npg, eb = g * epg;
    const int tid = threadIdx.x, lane = tid & 31, wid = tid >> 5;
    const int nw = blockDim.x >> 5;
    const int ei64 = g_flags[0], et64 = g_flags[1];

    for (int i = tid; i < nb; i += blockDim.x) cnt[i] = 0;
    __syncthreads();

    // phase 1: count buckets, cache bucket id per edge
    for (int e = tid; e < epg; e += blockDim.x) {
        int dst = (int)ldidx(ei, (size_t)E + eb + e, ei64);
        int t   = (int)ldidx(et, (size_t)(eb + e), et64);
        int b = (dst - bn) * RELC + t;
        ebuck[e] = b;
        atomicAdd(&cnt[b], 1);
    }
    __syncthreads();

    // phase 2: exclusive prefix scan over nb buckets
    const int C = (nb + blockDim.x - 1) / blockDim.x;
    int start = tid * C, end = start + C; if (end > nb) end = nb; if (start > nb) start = nb;
    int s = 0;
    for (int i = start; i < end; i++) s += cnt[i];
    int v = s;
#pragma unroll
    for (int d = 1; d < 32; d <<= 1) { int n = __shfl_up_sync(~0u, v, d); if (lane >= d) v += n; }
    if (lane == 31) ws[wid] = v;
    __syncthreads();
    if (wid == 0) {
        int w = (lane < 8) ? ws[lane] : 0;
#pragma unroll
        for (int d = 1; d < 8; d <<= 1) { int n = __shfl_up_sync(~0u, w, d); if (lane >= d) w += n; }
        if (lane < 8) ws[lane] = w;
    }
    __syncthreads();
    int run = v - s + (wid ? ws[wid - 1] : 0);
    for (int i = start; i < end; i++) { offs[i] = run; cursor[i] = run; run += cnt[i]; }
    __syncthreads();

    // phase 3: scatter src ids into bucket-sorted order
    for (int e = tid; e < epg; e += blockDim.x) {
        int src = (int)ldidx(ei, (size_t)(eb + e), ei64);
        int pos = atomicAdd(&cursor[ebuck[e]], 1);
        esrc[pos] = src;
    }
    __syncthreads();

    // phase 4: per-(dst,rel) register gather-mean; write g_agg
    for (int m = wid; m < npg; m += nw) {
        const size_t node = (size_t)(bn + m);
        float* orow = &g_agg[node * KTOT];
#pragma unroll
        for (int r = 0; r < RELC; r++) {
            int b = m * RELC + r;
            int o0 = offs[b], n = cnt[b];
            float4 acc = make_float4(0.f, 0.f, 0.f, 0.f);
            for (int i = 0; i < n; i++) {
                int src = esrc[o0 + i];
                float4 hv = *reinterpret_cast<const float4*>(&hin[(size_t)src * EMBC + lane * 4]);
                acc.x += hv.x; acc.y += hv.y; acc.z += hv.z; acc.w += hv.w;
            }
            if (n > 0) {
                float inv = 1.0f / (float)n;
                acc.x *= inv; acc.y *= inv; acc.z *= inv; acc.w *= inv;
            }
            *reinterpret_cast<float4*>(&orow[r * EMBC + lane * 4]) = acc;
        }
        // block 8: copy of hin row (root transform input)
        *reinterpret_cast<float4*>(&orow[RELC * EMBC + lane * 4]) =
            *reinterpret_cast<const float4*>(&hin[node * EMBC + lane * 4]);
    }
}

// ---------------------------------------------------------------------------
// GEMM via mma.sync tf32 3-term split: g_h[M,128] = relu?(g_agg[M,1152] @ B + bias)
// CTA: 256 thr (8 warps, 2x4 m/n), tile 128x128 out. K tiles of 32, cp.async
// double-buffered.
// smem floats: As[2][128][36] (18432 B each) then Bs[2][2][32][136] (34816 B each)
// A frag banks: 4*row+k unique; B frag banks: 8*k+n unique (strides 36 / 136).
// ---------------------------------------------------------------------------
#define AS_F 4608          // floats per A buffer (128*36)
#define BS_F 8704          // floats per B buffer (2*32*136)
#define BS_SPLIT 4352      // floats per hi/lo split (32*136)
#define SMEM_GEMM ((2 * AS_F + 2 * BS_F) * 4)  // 106,496 B

__global__ void __launch_bounds__(256)
gemm_mma_kernel(const float* __restrict__ bias, int layer, int M, int do_relu) {
    extern __shared__ float sm[];
    const u32 sbase = smem_to_u32(sm);
    const int tid = threadIdx.x, lane = tid & 31, wid = tid >> 5;
    const int warp_m = wid >> 2, warp_n = wid & 3;
    const int m0 = blockIdx.x * 128;

    const u32* WtL = g_Wt + (size_t)layer * NKT * 2 * (KC * EMBC);

    // --- cp.async tile loader ---
    auto issue_tile = [&](int t, int b) {
        // A: 128 rows x 32 floats = 1024 x 16B chunks
#pragma unroll
        for (int j = 0; j < 4; j++) {
            int c = j * 256 + tid;
            int row = c >> 3, ch = c & 7;
            u32 dst = sbase + (u32)(b * AS_F + row * 36 + ch * 4) * 4;
            cp16(dst, &g_agg[(size_t)(m0 + row) * KTOT + t * KC + ch * 4]);
        }
        // B: 2 splits x 32 rows x 128 u32 = 2048 x 16B chunks
        const u32* wb = WtL + (size_t)t * 2 * (KC * EMBC);
#pragma unroll
        for (int j = 0; j < 8; j++) {
            int c = j * 256 + tid;
            int s = c >> 10, rem = c & 1023;
            int kk = rem >> 5, ch = rem & 31;
            u32 dst = sbase + (u32)(2 * AS_F + b * BS_F + s * BS_SPLIT + kk * 136 + ch * 4) * 4;
            cp16(dst, wb + (size_t)s * (KC * EMBC) + kk * EMBC + ch * 4);
        }
    };

    float acc[4][4][4];
#pragma unroll
    for (int i = 0; i < 4; i++)
#pragma unroll
        for (int j = 0; j < 4; j++)
#pragma unroll
            for (int c = 0; c < 4; c++) acc[i][j][c] = 0.0f;

    issue_tile(0, 0);
    CP_COMMIT();

    for (int t = 0; t < NKT; t++) {
        const int b = t & 1;
        if (t + 1 < NKT) { issue_tile(t + 1, (t + 1) & 1); CP_COMMIT(); CP_WAIT(1); }
        else { CP_WAIT(0); }
        __syncthreads();

        const float* Asb = sm + b * AS_F;
        const u32* Bsb = (const u32*)(sm + 2 * AS_F + b * BS_F);

#pragma unroll
        for (int step = 0; step < 4; step++) {
            const int k8 = step * 8;
            // A fragments (hi/lo split in registers)
            u32 ah[4][4], al[4][4];
#pragma unroll
            for (int mt = 0; mt < 4; mt++) {
                int base = (warp_m * 64 + mt * 16 + (lane >> 2)) * 36 + k8 + (lane & 3);
                float a0 = Asb[base];
                float a1 = Asb[base + 8 * 36];
                float a2 = Asb[base + 4];
                float a3 = Asb[base + 8 * 36 + 4];
                ah[mt][0] = f2tf(a0); al[mt][0] = f2tf(a0 - __uint_as_float(ah[mt][0]));
                ah[mt][1] = f2tf(a1); al[mt][1] = f2tf(a1 - __uint_as_float(ah[mt][1]));
                ah[mt][2] = f2tf(a2); al[mt][2] = f2tf(a2 - __uint_as_float(ah[mt][2]));
                ah[mt][3] = f2tf(a3); al[mt][3] = f2tf(a3 - __uint_as_float(ah[mt][3]));
            }
            // B fragments (pre-split)
            u32 bh[4][2], bl[4][2];
#pragma unroll
            for (int nt = 0; nt < 4; nt++) {
                int col = warp_n * 32 + nt * 8 + (lane >> 2);
                int bidx = (k8 + (lane & 3)) * 136 + col;
                bh[nt][0] = Bsb[bidx];
                bh[nt][1] = Bsb[bidx + 4 * 136];
                bl[nt][0] = Bsb[bidx + BS_SPLIT];
                bl[nt][1] = Bsb[bidx + BS_SPLIT + 4 * 136];
            }
            // 3-term tf32 MMAs
#pragma unroll
            for (int mt = 0; mt < 4; mt++)
#pragma unroll
                for (int nt = 0; nt < 4; nt++) {
                    float* c = acc[mt][nt];
                    mma_tf32(c[0], c[1], c[2], c[3],
                             ah[mt][0], ah[mt][1], ah[mt][2], ah[mt][3], bh[nt][0], bh[nt][1]);
                    mma_tf32(c[0], c[1], c[2], c[3],
                             ah[mt][0], ah[mt][1], ah[mt][2], ah[mt][3], bl[nt][0], bl[nt][1]);
                    mma_tf32(c[0], c[1], c[2], c[3],
                             al[mt][0], al[mt][1], al[mt][2], al[mt][3], bh[nt][0], bh[nt][1]);
                }
        }
        __syncthreads();
    }

    // epilogue: bias (+relu) -> g_h
#pragma unroll
    for (int mt = 0; mt < 4; mt++) {
        int row0 = m0 + warp_m * 64 + mt * 16 + (lane >> 2);
#pragma unroll
        for (int nt = 0; nt < 4; nt++) {
            int col = warp_n * 32 + nt * 8 + 2 * (lane & 3);
            float bx = bias[col], by = bias[col + 1];
            float* c = acc[mt][nt];
            float2 v0 = make_float2(c[0] + bx, c[1] + by);
            float2 v1 = make_float2(c[2] + bx, c[3] + by);
            if (do_relu) {
                v0.x = fmaxf(v0.x, 0.f); v0.y = fmaxf(v0.y, 0.f);
                v1.x = fmaxf(v1.x, 0.f); v1.y = fmaxf(v1.y, 0.f);
            }
            if (row0 < M)
                *reinterpret_cast<float2*>(&g_h[(size_t)row0 * EMBC + col]) = v0;
            if (row0 + 8 < M)
                *reinterpret_cast<float2*>(&g_h[(size_t)(row0 + 8) * EMBC + col]) = v1;
        }
    }
}

// ---------------------------------------------------------------------------
// Score: logits[g, pos] = dot(node_emb[n], message_repr[g]); one warp per node
// ---------------------------------------------------------------------------
__global__ void score_kernel(float* __restrict__ outp, int n_nodes, int npg, int max_nodes) {
    const int wid = threadIdx.x >> 5, lane = threadIdx.x & 31;
    const int n = blockIdx.x * 8 + wid;
    if (n >= n_nodes) return;
    const int g = n / npg, pos = n - g * npg;
    float4 e = *reinterpret_cast<const float4*>(&g_h[(size_t)n * EMBC + lane * 4]);
    float4 m = *reinterpret_cast<const float4*>(&g_msg[(size_t)g * EMBC + lane * 4]);
    float p = e.x * m.x + e.y * m.y + e.z * m.z + e.w * m.w;
#pragma unroll
    for (int s = 16; s > 0; s >>= 1) p += __shfl_down_sync(~0u, p, s);
    if (lane == 0) outp[(size_t)g * max_nodes + pos] = p;
}

__global__ void pad_kernel(float* __restrict__ outp, int n_graphs, int npg, int max_nodes) {
    int i = blockIdx.x * blockDim.x + threadIdx.x;
    int per = max_nodes - npg;
    if (i >= n_graphs * per) return;
    int g = i / per, pos = npg + (i - g * per);
    outp[(size_t)g * max_nodes + pos] = -INFINITY;
}

// ---------------------------------------------------------------------------
// Launch.  Inputs: 0 message, 1 x, 2 edge_index, 3 edge_type, 4 batch,
// 5 max_nodes, 6 W1, 7 root1, 8 b1, 9 W2, 10 root2, 11 b2, 12 embed_table,
// 13 cont_w, 14 cont_b, 15 msg_w, 16 msg_b
// ---------------------------------------------------------------------------
extern "C" void kernel_launch(void* const* d_in, const int* in_sizes, int n_in,
                              void* d_out, int out_size) {
    const float* message = (const float*)d_in[0];
    const float* x       = (const float*)d_in[1];
    const void*  ei      = d_in[2];
    const void*  et      = d_in[3];
    const float* W1      = (const float*)d_in[6];
    const float* r1      = (const float*)d_in[7];
    const float* b1      = (const float*)d_in[8];
    const float* W2      = (const float*)d_in[9];
    const float* r2      = (const float*)d_in[10];
    const float* b2      = (const float*)d_in[11];
    const float* emb     = (const float*)d_in[12];
    const float* cw      = (const float*)d_in[13];
    const float* cbv     = (const float*)d_in[14];
    const float* mw      = (const float*)d_in[15];
    const float* mb      = (const float*)d_in[16];

    const int n_graphs  = in_sizes[0] / 2;
    const int n_nodes   = in_sizes[4];
    const int E         = in_sizes[3];
    const int vocab     = in_sizes[12] / EMBC;
    const int npg       = n_nodes / n_graphs;
    const int epg       = E / n_graphs;
    const int max_nodes = out_size / n_graphs;
    float* outp = (float*)d_out;

    const size_t agg_sm = (size_t)npg * RELC * 3 * sizeof(int) + (size_t)epg * 2 * sizeof(int) + 64;
    cudaFuncSetAttribute(agg_kernel, cudaFuncAttributeMaxDynamicSharedMemorySize, (int)agg_sm);
    cudaFuncSetAttribute(gemm_mma_kernel, cudaFuncAttributeMaxDynamicSharedMemorySize, SMEM_GEMM);

    detect_kernel<<<1, 256>>>((const u32*)ei, (const u32*)et);
    repack_kernel<<<(2 * KTOT * EMBC + 255) / 256, 256>>>(W1, r1, W2, r2);
    msg_kernel<<<n_graphs, EMBC>>>(message, emb, cw, cbv, mw, mb, vocab);

    const int MB = (n_nodes + 127) / 128;

    // layer 1
    agg_kernel<<<n_graphs, 256, agg_sm>>>(x, 0, ei, et, npg, epg, E);
    gemm_mma_kernel<<<MB, 256, SMEM_GEMM>>>(b1, 0, n_nodes, 1);
    // layer 2
    agg_kernel<<<n_graphs, 256, agg_sm>>>(x, 1, ei, et, npg, epg, E);
    gemm_mma_kernel<<<MB, 256, SMEM_GEMM>>>(b2, 1, n_nodes, 0);

    score_kernel<<<(n_nodes + 7) / 8, 256>>>(outp, n_nodes, npg, max_nodes);
    if (max_nodes > npg) {
        int pad = n_graphs * (max_nodes - npg);
        pad_kernel<<<(pad + 255) / 256, 256>>>(outp, n_graphs, npg, max_nodes);
    }
}

// round 15
// speedup vs baseline: 2.5735x; 1.0784x over previous
#include <cuda_runtime.h>
#include <cuda_bf16.h>
#include <stdint.h>
#include <math.h>

typedef unsigned int u32;
typedef unsigned long long u64;

// ---------------------------------------------------------------------------
// Problem constants
// ---------------------------------------------------------------------------
#define EMBC 128                   // F_IN == EMB == HID == 128
#define RELC 8                     // N_REL
#define KTOT ((RELC + 1) * EMBC)   // 1152 : GEMM K (8 rel blocks + root block)
#define KAGG (RELC * EMBC)         // 1024 : g_agg row (rel blocks only)
#define KC   32                    // K per smem tile
#define NKT  (KTOT / KC)           // 36 tiles; tiles 32..35 come from hin (root)
#define TROOT 32
#define MAXN 50176
#define MAXG 256
#define MAXE (1 << 20)

// ---------------------------------------------------------------------------
// Scratch (device globals: no allocation allowed)
// ---------------------------------------------------------------------------
__device__ float g_agg[(size_t)MAXN * KAGG];   // [N,1024] per-(node,rel) bucket means
__device__ float g_h[(size_t)MAXN * EMBC];     // layer output (h1, then node_emb)
__device__ float g_msg[MAXG * EMBC];           // message_repr per graph
__device__ u32   g_Wt[2 * NKT * 2 * KC * EMBC]; // tf32 B tiles [layer][kt][hi/lo][32][128]
__device__ int   g_off[MAXN * RELC];           // CSR bucket start (absolute into g_esrc)
__device__ int   g_cnt8[MAXN * RELC];          // CSR bucket count
__device__ int   g_esrc[MAXE];                 // bucket-sorted src node ids
__device__ int   g_flags[4];                   // [0]=edge_index int64, [1]=edge_type int64

// ---------------------------------------------------------------------------
// PTX helpers (plain sm_103 features only: cp.async + mma.sync)
// ---------------------------------------------------------------------------
__device__ __forceinline__ u32 smem_to_u32(const void* p) {
    u32 a;
    asm("{ .reg .u64 t; cvta.to.shared.u64 t, %1; cvt.u32.u64 %0, t; }" : "=r"(a) : "l"(p));
    return a;
}
__device__ __forceinline__ void cp16(u32 dst, const void* src) {
    asm volatile("cp.async.cg.shared.global [%0], [%1], 16;" :: "r"(dst), "l"(src));
}
#define CP_COMMIT() asm volatile("cp.async.commit_group;" ::: "memory")
#define CP_WAIT(n)  asm volatile("cp.async.wait_group %0;" :: "n"(n) : "memory")

__device__ __forceinline__ u32 f2tf(float f) {
    u32 r;
    asm("cvt.rna.tf32.f32 %0, %1;" : "=r"(r) : "f"(f));
    return r;
}
__device__ __forceinline__ void mma_tf32(float& c0, float& c1, float& c2, float& c3,
                                         u32 a0, u32 a1, u32 a2, u32 a3, u32 b0, u32 b1) {
    asm("mma.sync.aligned.m16n8k8.row.col.f32.tf32.tf32.f32 "
        "{%0,%1,%2,%3}, {%4,%5,%6,%7}, {%8,%9}, {%0,%1,%2,%3};"
        : "+f"(c0), "+f"(c1), "+f"(c2), "+f"(c3)
        : "r"(a0), "r"(a1), "r"(a2), "r"(a3), "r"(b0), "r"(b1));
}

// ---------------------------------------------------------------------------
// index width helpers
// ---------------------------------------------------------------------------
__device__ __forceinline__ long long ldidx(const void* p, size_t i, int is64) {
    return is64 ? ((const long long*)p)[i] : (long long)((const int*)p)[i];
}

__global__ void detect_kernel(const u32* ei, const u32* et) {
    __shared__ u32 s[2];
    if (threadIdx.x < 2) s[threadIdx.x] = 0u;
    __syncthreads();
    u32 a = 0u, b = 0u;
    for (int i = threadIdx.x; i < 1024; i += blockDim.x) { a |= ei[2 * i + 1]; b |= et[2 * i + 1]; }
    atomicOr(&s[0], a); atomicOr(&s[1], b);
    __syncthreads();
    if (threadIdx.x == 0) { g_flags[0] = (s[0] == 0u); g_flags[1] = (s[1] == 0u); }
}

// ---------------------------------------------------------------------------
// Repack weights into tf32 hi/lo tiles: B[k=r*128+f][n=o] = W_r[f][o], root r=8.
// ---------------------------------------------------------------------------
__global__ void repack_kernel(const float* __restrict__ W1, const float* __restrict__ r1,
                              const float* __restrict__ W2, const float* __restrict__ r2) {
    int i = blockIdx.x * blockDim.x + threadIdx.x;
    if (i >= 2 * KTOT * EMBC) return;
    int layer = i / (KTOT * EMBC);
    int rem = i - layer * (KTOT * EMBC);
    int k = rem / EMBC;
    int n = rem - k * EMBC;
    int r = k >> 7, f = k & 127;
    const float* W = layer ? W2 : W1;
    const float* rt = layer ? r2 : r1;
    float v = (r < RELC) ? W[((size_t)r * EMBC + f) * EMBC + n] : rt[(size_t)f * EMBC + n];
    u32 hi = f2tf(v);
    u32 lo = f2tf(v - __uint_as_float(hi));
    int kt = k / KC, kk = k - kt * KC;
    size_t base = (((size_t)layer * NKT + kt) * 2) * (KC * EMBC) + (size_t)kk * EMBC + n;
    g_Wt[base] = hi;
    g_Wt[base + KC * EMBC] = lo;
}

// ---------------------------------------------------------------------------
// message_repr: one block (128 threads) per graph
// ---------------------------------------------------------------------------
__global__ void msg_kernel(const float* __restrict__ message, const float* __restrict__ embed,
                           const float* __restrict__ cw, const float* __restrict__ cb,
                           const float* __restrict__ mw, const float* __restrict__ mb, int vocab) {
    __shared__ float s[2 * EMBC];
    int g = blockIdx.x, o = threadIdx.x;
    int tok = (int)message[(size_t)g * 2];
    float cont = message[(size_t)g * 2 + 1];
    if (tok < 0) tok = 0;
    if (tok >= vocab) tok = vocab - 1;
    s[o] = embed[(size_t)tok * EMBC + o];
    s[EMBC + o] = fmaxf(cont * cw[o] + cb[o], 0.0f);
    __syncthreads();
    float acc = mb[o];
#pragma unroll 8
    for (int j = 0; j < 2 * EMBC; j++) acc += s[j] * mw[(size_t)j * EMBC + o];
    g_msg[(size_t)g * EMBC + o] = fmaxf(acc, 0.0f);
}

// ---------------------------------------------------------------------------
// CSR build (ONCE — shared by both layers): per-graph CTA, smem count/scan/
// scatter, results to global (g_off absolute, g_cnt8, g_esrc bucket-sorted).
// ---------------------------------------------------------------------------
__global__ void __launch_bounds__(256)
csr_kernel(const void* __restrict__ ei, const void* __restrict__ et,
           int npg, int epg, int E) {
    extern __shared__ int smi[];
    const int nb = npg * RELC;
    int* cnt    = smi;             // nb
    int* offs   = cnt + nb;        // nb
    int* cursor = offs + nb;       // nb
    int* ebuck  = cursor + nb;     // epg
    __shared__ int ws[8];

    const int g = blockIdx.x, bn = g * npg, eb = g * epg;
    const int tid = threadIdx.x, lane = tid & 31, wid = tid >> 5;
    const int ei64 = g_flags[0], et64 = g_flags[1];

    for (int i = tid; i < nb; i += blockDim.x) cnt[i] = 0;
    __syncthreads();

    // count buckets
    for (int e = tid; e < epg; e += blockDim.x) {
        int dst = (int)ldidx(ei, (size_t)E + eb + e, ei64);
        int t   = (int)ldidx(et, (size_t)(eb + e), et64);
        int b = (dst - bn) * RELC + t;
        ebuck[e] = b;
        atomicAdd(&cnt[b], 1);
    }
    __syncthreads();

    // exclusive prefix scan over nb buckets
    const int C = (nb + blockDim.x - 1) / blockDim.x;
    int start = tid * C, end = start + C; if (end > nb) end = nb; if (start > nb) start = nb;
    int s = 0;
    for (int i = start; i < end; i++) s += cnt[i];
    int v = s;
#pragma unroll
    for (int d = 1; d < 32; d <<= 1) { int n = __shfl_up_sync(~0u, v, d); if (lane >= d) v += n; }
    if (lane == 31) ws[wid] = v;
    __syncthreads();
    if (wid == 0) {
        int w = (lane < 8) ? ws[lane] : 0;
#pragma unroll
        for (int d = 1; d < 8; d <<= 1) { int n = __shfl_up_sync(~0u, w, d); if (lane >= d) w += n; }
        if (lane < 8) ws[lane] = w;
    }
    __syncthreads();
    int run = v - s + (wid ? ws[wid - 1] : 0);
    for (int i = start; i < end; i++) { offs[i] = run; cursor[i] = run; run += cnt[i]; }
    __syncthreads();

    // scatter src ids + publish CSR
    for (int e = tid; e < epg; e += blockDim.x) {
        int src = (int)ldidx(ei, (size_t)(eb + e), ei64);
        int pos = atomicAdd(&cursor[ebuck[e]], 1);
        g_esrc[eb + pos] = src;
    }
    for (int i = tid; i < nb; i += blockDim.x) {
        g_off[bn * RELC + i]  = eb + offs[i];
        g_cnt8[bn * RELC + i] = cnt[i];
    }
}

// ---------------------------------------------------------------------------
// Gather: one warp per node (high parallelism). g_agg[n, r*128+:] =
// mean over bucket (n,r) of hin rows. useH selects g_h as input.
// ---------------------------------------------------------------------------
__global__ void __launch_bounds__(256)
gather_kernel(const float* __restrict__ xext, int useH, int n_nodes) {
    const float* __restrict__ hin = useH ? (const float*)g_h : xext;
    const int wid = threadIdx.x >> 5, lane = threadIdx.x & 31;
    const int n = blockIdx.x * 8 + wid;
    if (n >= n_nodes) return;
    float* orow = &g_agg[(size_t)n * KAGG];
#pragma unroll
    for (int r = 0; r < RELC; r++) {
        int b = n * RELC + r;
        int o0 = g_off[b], cn = g_cnt8[b];
        float4 acc = make_float4(0.f, 0.f, 0.f, 0.f);
        for (int i = 0; i < cn; i++) {
            int src = g_esrc[o0 + i];
            float4 hv = *reinterpret_cast<const float4*>(&hin[(size_t)src * EMBC + lane * 4]);
            acc.x += hv.x; acc.y += hv.y; acc.z += hv.z; acc.w += hv.w;
        }
        if (cn > 0) {
            float inv = 1.0f / (float)cn;
            acc.x *= inv; acc.y *= inv; acc.z *= inv; acc.w *= inv;
        }
        *reinterpret_cast<float4*>(&orow[r * EMBC + lane * 4]) = acc;
    }
}

// ---------------------------------------------------------------------------
// GEMM via mma.sync tf32 3-term split: g_h[M,128] = relu?(A[M,1152] @ B + bias)
// A = [g_agg | hin-root-block]. CTA: 512 thr (16 warps, 4x4 m/n), tile 128x128.
// K tiles of 32, cp.async double-buffered; tiles 32..35 read from hin (row-clamped).
// smem floats: As[2][128][36] then Bs[2][2][32][136]; conflict-free frags.
// ---------------------------------------------------------------------------
#define AS_F 4608          // floats per A buffer (128*36)
#define BS_F 8704          // floats per B buffer (2*32*136)
#define BS_SPLIT 4352      // floats per hi/lo split (32*136)
#define SMEM_GEMM ((2 * AS_F + 2 * BS_F) * 4)  // 106,496 B

__global__ void __launch_bounds__(512)
gemm_mma_kernel(const float* __restrict__ bias, const float* __restrict__ xext,
                int useH, int layer, int M, int do_relu) {
    const float* __restrict__ hsrc = useH ? (const float*)g_h : xext;
    extern __shared__ float sm[];
    const u32 sbase = smem_to_u32(sm);
    const int tid = threadIdx.x, lane = tid & 31, wid = tid >> 5;
    const int warp_m = wid >> 2, warp_n = wid & 3;
    const int m0 = blockIdx.x * 128;

    const u32* WtL = g_Wt + (size_t)layer * NKT * 2 * (KC * EMBC);

    auto issue_tile = [&](int t, int b) {
        // A: 128 rows x 32 floats = 1024 x 16B chunks (512 thr -> 2 iters)
#pragma unroll
        for (int j = 0; j < 2; j++) {
            int c = j * 512 + tid;
            int row = c >> 3, ch = c & 7;
            int grow = m0 + row; if (grow >= M) grow = M - 1;  // clamp (hin has N rows)
            u32 dst = sbase + (u32)(b * AS_F + row * 36 + ch * 4) * 4;
            const float* src = (t < TROOT)
                ? &g_agg[(size_t)grow * KAGG + t * KC + ch * 4]
                : &hsrc[(size_t)grow * EMBC + (t - TROOT) * KC + ch * 4];
            cp16(dst, src);
        }
        // B: 2 splits x 32 rows x 128 u32 = 2048 x 16B chunks (4 iters)
        const u32* wb = WtL + (size_t)t * 2 * (KC * EMBC);
#pragma unroll
        for (int j = 0; j < 4; j++) {
            int c = j * 512 + tid;
            int s = c >> 10, rem = c & 1023;
            int kk = rem >> 5, ch = rem & 31;
            u32 dst = sbase + (u32)(2 * AS_F + b * BS_F + s * BS_SPLIT + kk * 136 + ch * 4) * 4;
            cp16(dst, wb + (size_t)s * (KC * EMBC) + kk * EMBC + ch * 4);
        }
    };

    float acc[2][4][4];
#pragma unroll
    for (int i = 0; i < 2; i++)
#pragma unroll
        for (int j = 0; j < 4; j++)
#pragma unroll
            for (int c = 0; c < 4; c++) acc[i][j][c] = 0.0f;

    issue_tile(0, 0);
    CP_COMMIT();

    for (int t = 0; t < NKT; t++) {
        const int b = t & 1;
        if (t + 1 < NKT) { issue_tile(t + 1, (t + 1) & 1); CP_COMMIT(); CP_WAIT(1); }
        else { CP_WAIT(0); }
        __syncthreads();

        const float* Asb = sm + b * AS_F;
        const u32* Bsb = (const u32*)(sm + 2 * AS_F + b * BS_F);

#pragma unroll
        for (int step = 0; step < 4; step++) {
            const int k8 = step * 8;
            u32 ah[2][4], al[2][4];
#pragma unroll
            for (int mt = 0; mt < 2; mt++) {
                int base = (warp_m * 32 + mt * 16 + (lane >> 2)) * 36 + k8 + (lane & 3);
                float a0 = Asb[base];
                float a1 = Asb[base + 8 * 36];
                float a2 = Asb[base + 4];
                float a3 = Asb[base + 8 * 36 + 4];
                ah[mt][0] = f2tf(a0); al[mt][0] = f2tf(a0 - __uint_as_float(ah[mt][0]));
                ah[mt][1] = f2tf(a1); al[mt][1] = f2tf(a1 - __uint_as_float(ah[mt][1]));
                ah[mt][2] = f2tf(a2); al[mt][2] = f2tf(a2 - __uint_as_float(ah[mt][2]));
                ah[mt][3] = f2tf(a3); al[mt][3] = f2tf(a3 - __uint_as_float(ah[mt][3]));
            }
            u32 bh[4][2], bl[4][2];
#pragma unroll
            for (int nt = 0; nt < 4; nt++) {
                int col = warp_n * 32 + nt * 8 + (lane >> 2);
                int bidx = (k8 + (lane & 3)) * 136 + col;
                bh[nt][0] = Bsb[bidx];
                bh[nt][1] = Bsb[bidx + 4 * 136];
                bl[nt][0] = Bsb[bidx + BS_SPLIT];
                bl[nt][1] = Bsb[bidx + BS_SPLIT + 4 * 136];
            }
#pragma unroll
            for (int mt = 0; mt < 2; mt++)
#pragma unroll
                for (int nt = 0; nt < 4; nt++) {
                    float* c = acc[mt][nt];
                    mma_tf32(c[0], c[1], c[2], c[3],
                             ah[mt][0], ah[mt][1], ah[mt][2], ah[mt][3], bh[nt][0], bh[nt][1]);
                    mma_tf32(c[0], c[1], c[2], c[3],
                             ah[mt][0], ah[mt][1], ah[mt][2], ah[mt][3], bl[nt][0], bl[nt][1]);
                    mma_tf32(c[0], c[1], c[2], c[3],
                             al[mt][0], al[mt][1], al[mt][2], al[mt][3], bh[nt][0], bh[nt][1]);
                }
        }
        __syncthreads();
    }

    // epilogue: bias (+relu) -> g_h
#pragma unroll
    for (int mt = 0; mt < 2; mt++) {
        int row0 = m0 + warp_m * 32 + mt * 16 + (lane >> 2);
#pragma unroll
        for (int nt = 0; nt < 4; nt++) {
            int col = warp_n * 32 + nt * 8 + 2 * (lane & 3);
            float bx = bias[col], by = bias[col + 1];
            float* c = acc[mt][nt];
            float2 v0 = make_float2(c[0] + bx, c[1] + by);
            float2 v1 = make_float2(c[2] + bx, c[3] + by);
            if (do_relu) {
                v0.x = fmaxf(v0.x, 0.f); v0.y = fmaxf(v0.y, 0.f);
                v1.x = fmaxf(v1.x, 0.f); v1.y = fmaxf(v1.y, 0.f);
            }
            if (row0 < M)
                *reinterpret_cast<float2*>(&g_h[(size_t)row0 * EMBC + col]) = v0;
            if (row0 + 8 < M)
                *reinterpret_cast<float2*>(&g_h[(size_t)(row0 + 8) * EMBC + col]) = v1;
        }
    }
}

// ---------------------------------------------------------------------------
// Score: logits[g, pos] = dot(node_emb[n], message_repr[g]); one warp per node
// ---------------------------------------------------------------------------
__global__ void score_kernel(float* __restrict__ outp, int n_nodes, int npg, int max_nodes) {
    const int wid = threadIdx.x >> 5, lane = threadIdx.x & 31;
    const int n = blockIdx.x * 8 + wid;
    if (n >= n_nodes) return;
    const int g = n / npg, pos = n - g * npg;
    float4 e = *reinterpret_cast<const float4*>(&g_h[(size_t)n * EMBC + lane * 4]);
    float4 m = *reinterpret_cast<const float4*>(&g_msg[(size_t)g * EMBC + lane * 4]);
    float p = e.x * m.x + e.y * m.y + e.z * m.z + e.w * m.w;
#pragma unroll
    for (int s = 16; s > 0; s >>= 1) p += __shfl_down_sync(~0u, p, s);
    if (lane == 0) outp[(size_t)g * max_nodes + pos] = p;
}

__global__ void pad_kernel(float* __restrict__ outp, int n_graphs, int npg, int max_nodes) {
    int i = blockIdx.x * blockDim.x + threadIdx.x;
    int per = max_nodes - npg;
    if (i >= n_graphs * per) return;
    int g = i / per, pos = npg + (i - g * per);
    outp[(size_t)g * max_nodes + pos] = -INFINITY;
}

// ---------------------------------------------------------------------------
// Launch.  Inputs: 0 message, 1 x, 2 edge_index, 3 edge_type, 4 batch,
// 5 max_nodes, 6 W1, 7 root1, 8 b1, 9 W2, 10 root2, 11 b2, 12 embed_table,
// 13 cont_w, 14 cont_b, 15 msg_w, 16 msg_b
// ---------------------------------------------------------------------------
extern "C" void kernel_launch(void* const* d_in, const int* in_sizes, int n_in,
                              void* d_out, int out_size) {
    const float* message = (const float*)d_in[0];
    const float* x       = (const float*)d_in[1];
    const void*  ei      = d_in[2];
    const void*  et      = d_in[3];
    const float* W1      = (const float*)d_in[6];
    const float* r1      = (const float*)d_in[7];
    const float* b1      = (const float*)d_in[8];
    const float* W2      = (const float*)d_in[9];
    const float* r2      = (const float*)d_in[10];
    const float* b2      = (const float*)d_in[11];
    const float* emb     = (const float*)d_in[12];
    const float* cw      = (const float*)d_in[13];
    const float* cbv     = (const float*)d_in[14];
    const float* mw      = (const float*)d_in[15];
    const float* mb      = (const float*)d_in[16];

    const int n_graphs  = in_sizes[0] / 2;
    const int n_nodes   = in_sizes[4];
    const int E         = in_sizes[3];
    const int vocab     = in_sizes[12] / EMBC;
    const int npg       = n_nodes / n_graphs;
    const int epg       = E / n_graphs;
    const int max_nodes = out_size / n_graphs;
    float* outp = (float*)d_out;

    const size_t csr_sm = ((size_t)npg * RELC * 3 + epg) * sizeof(int) + 64;
    cudaFuncSetAttribute(csr_kernel, cudaFuncAttributeMaxDynamicSharedMemorySize, (int)csr_sm);
    cudaFuncSetAttribute(gemm_mma_kernel, cudaFuncAttributeMaxDynamicSharedMemorySize, SMEM_GEMM);

    detect_kernel<<<1, 256>>>((const u32*)ei, (const u32*)et);
    repack_kernel<<<(2 * KTOT * EMBC + 255) / 256, 256>>>(W1, r1, W2, r2);
    msg_kernel<<<n_graphs, EMBC>>>(message, emb, cw, cbv, mw, mb, vocab);
    csr_kernel<<<n_graphs, 256, csr_sm>>>(ei, et, npg, epg, E);

    const int MB = (n_nodes + 127) / 128;
    const int GB = (n_nodes + 7) / 8;

    // layer 1
    gather_kernel<<<GB, 256>>>(x, 0, n_nodes);
    gemm_mma_kernel<<<MB, 512, SMEM_GEMM>>>(b1, x, 0, 0, n_nodes, 1);
    // layer 2
    gather_kernel<<<GB, 256>>>(x, 1, n_nodes);
    gemm_mma_kernel<<<MB, 512, SMEM_GEMM>>>(b2, x, 1, 1, n_nodes, 0);

    score_kernel<<<GB, 256>>>(outp, n_nodes, npg, max_nodes);
    if (max_nodes > npg) {
        int pad = n_graphs * (max_nodes - npg);
        pad_kernel<<<(pad + 255) / 256, 256>>>(outp, n_graphs, npg, max_nodes);
    }
}

// round 17
// speedup vs baseline: 3.7428x; 1.4544x over previous
#include <cuda_runtime.h>
#include <cuda_fp16.h>
#include <stdint.h>
#include <math.h>

typedef unsigned int u32;
typedef unsigned long long u64;

// ---------------------------------------------------------------------------
// Problem constants
// ---------------------------------------------------------------------------
#define EMBC 128                   // F_IN == EMB == HID == 128
#define RELC 8                     // N_REL
#define KTOT ((RELC + 1) * EMBC)   // 1152 : GEMM K (8 rel blocks + root block)
#define NPAIR (KTOT / 2)           // 576 fp16 k-pairs per row per plane
#define KC   32                    // K per smem tile (16 pairs)
#define NKT  (KTOT / KC)           // 36 tiles (root included -> uniform A path)
#define MAXN 50176
#define MAXG 256
#define MAXE (1 << 20)
#define PLANE ((size_t)MAXN * NPAIR)

// ---------------------------------------------------------------------------
// Scratch (device globals: no allocation allowed)
// ---------------------------------------------------------------------------
__device__ u32   g_pk[2 * PLANE];              // packed fp16 k-pairs: [hi|lo][N][576]
__device__ float g_h[(size_t)MAXN * EMBC];     // layer output (h1, then node_emb)
__device__ float g_msg[MAXG * EMBC];           // message_repr per graph
__device__ u32   g_Wt[2 * NKT * 2 * 16 * EMBC]; // B tiles [layer][t][hi/lo][16 pairs][128]
__device__ int   g_off[MAXN * RELC];           // CSR bucket start (absolute into g_esrc)
__device__ int   g_cnt8[MAXN * RELC];          // CSR bucket count
__device__ int   g_esrc[MAXE];                 // bucket-sorted src node ids
__device__ int   g_flags[4];                   // [0]=edge_index int64, [1]=edge_type int64

// ---------------------------------------------------------------------------
// PTX helpers (plain sm_103 features only: cp.async + mma.sync)
// ---------------------------------------------------------------------------
__device__ __forceinline__ u32 smem_to_u32(const void* p) {
    u32 a;
    asm("{ .reg .u64 t; cvta.to.shared.u64 t, %1; cvt.u32.u64 %0, t; }" : "=r"(a) : "l"(p));
    return a;
}
__device__ __forceinline__ void cp16(u32 dst, const void* src) {
    asm volatile("cp.async.cg.shared.global [%0], [%1], 16;" :: "r"(dst), "l"(src));
}
#define CP_COMMIT() asm volatile("cp.async.commit_group;" ::: "memory")
#define CP_WAIT(n)  asm volatile("cp.async.wait_group %0;" :: "n"(n) : "memory")

__device__ __forceinline__ void mma_f16(float& c0, float& c1, float& c2, float& c3,
                                        u32 a0, u32 a1, u32 a2, u32 a3, u32 b0, u32 b1) {
    asm("mma.sync.aligned.m16n8k16.row.col.f32.f16.f16.f32 "
        "{%0,%1,%2,%3}, {%4,%5,%6,%7}, {%8,%9}, {%0,%1,%2,%3};"
        : "+f"(c0), "+f"(c1), "+f"(c2), "+f"(c3)
        : "r"(a0), "r"(a1), "r"(a2), "r"(a3), "r"(b0), "r"(b1));
}

// pack two floats into fp16 hi-pair and lo-pair u32s
__device__ __forceinline__ void pack_hl(float x, float y, u32& hp, u32& lp) {
    __half2 h2 = __floats2half2_rn(x, y);
    float2 hf = __half22float2(h2);
    __half2 l2 = __floats2half2_rn(x - hf.x, y - hf.y);
    hp = *reinterpret_cast<u32*>(&h2);
    lp = *reinterpret_cast<u32*>(&l2);
}

// ---------------------------------------------------------------------------
// index width helpers
// ---------------------------------------------------------------------------
__device__ __forceinline__ long long ldidx(const void* p, size_t i, int is64) {
    return is64 ? ((const long long*)p)[i] : (long long)((const int*)p)[i];
}

__global__ void detect_kernel(const u32* ei, const u32* et) {
    __shared__ u32 s[2];
    if (threadIdx.x < 2) s[threadIdx.x] = 0u;
    __syncthreads();
    u32 a = 0u, b = 0u;
    for (int i = threadIdx.x; i < 1024; i += blockDim.x) { a |= ei[2 * i + 1]; b |= et[2 * i + 1]; }
    atomicOr(&s[0], a); atomicOr(&s[1], b);
    __syncthreads();
    if (threadIdx.x == 0) { g_flags[0] = (s[0] == 0u); g_flags[1] = (s[1] == 0u); }
}

// ---------------------------------------------------------------------------
// Repack weights into fp16 hi/lo packed-pair tiles.
// B[k = r*128+f][n = o] = W_r[f][o], root r=8. Pair p covers k = 2p, 2p+1.
// g_Wt[((layer*NKT + t)*2 + plane)*2048 + pp*128 + n]
// ---------------------------------------------------------------------------
__global__ void repack_kernel(const float* __restrict__ W1, const float* __restrict__ r1,
                              const float* __restrict__ W2, const float* __restrict__ r2) {
    int i = blockIdx.x * blockDim.x + threadIdx.x;
    if (i >= 2 * NPAIR * EMBC) return;
    int layer = i / (NPAIR * EMBC);
    int rem = i - layer * (NPAIR * EMBC);
    int p = rem / EMBC;
    int n = rem - p * EMBC;
    int k0 = 2 * p, k1 = k0 + 1;
    int r = k0 >> 7, f0 = k0 & 127, f1 = k1 & 127;
    const float* W = layer ? W2 : W1;
    const float* rt = layer ? r2 : r1;
    float v0 = (r < RELC) ? W[((size_t)r * EMBC + f0) * EMBC + n] : rt[(size_t)f0 * EMBC + n];
    float v1 = (r < RELC) ? W[((size_t)r * EMBC + f1) * EMBC + n] : rt[(size_t)f1 * EMBC + n];
    u32 hp, lp;
    pack_hl(v0, v1, hp, lp);
    int t = p >> 4, pp = p & 15;
    size_t base = ((size_t)(layer * NKT + t) * 2) * 2048 + (size_t)pp * EMBC + n;
    g_Wt[base] = hp;          // hi plane
    g_Wt[base + 2048] = lp;   // lo plane
}

// ---------------------------------------------------------------------------
// message_repr: one block (128 threads) per graph
// ---------------------------------------------------------------------------
__global__ void msg_kernel(const float* __restrict__ message, const float* __restrict__ embed,
                           const float* __restrict__ cw, const float* __restrict__ cb,
                           const float* __restrict__ mw, const float* __restrict__ mb, int vocab) {
    __shared__ float s[2 * EMBC];
    int g = blockIdx.x, o = threadIdx.x;
    int tok = (int)message[(size_t)g * 2];
    float cont = message[(size_t)g * 2 + 1];
    if (tok < 0) tok = 0;
    if (tok >= vocab) tok = vocab - 1;
    s[o] = embed[(size_t)tok * EMBC + o];
    s[EMBC + o] = fmaxf(cont * cw[o] + cb[o], 0.0f);
    __syncthreads();
    float acc = mb[o];
#pragma unroll 8
    for (int j = 0; j < 2 * EMBC; j++) acc += s[j] * mw[(size_t)j * EMBC + o];
    g_msg[(size_t)g * EMBC + o] = fmaxf(acc, 0.0f);
}

// ---------------------------------------------------------------------------
// CSR build (ONCE — shared by both layers)
// ---------------------------------------------------------------------------
__global__ void __launch_bounds__(256)
csr_kernel(const void* __restrict__ ei, const void* __restrict__ et,
           int npg, int epg, int E) {
    extern __shared__ int smi[];
    const int nb = npg * RELC;
    int* cnt    = smi;
    int* offs   = cnt + nb;
    int* cursor = offs + nb;
    int* ebuck  = cursor + nb;
    __shared__ int ws[8];

    const int g = blockIdx.x, bn = g * npg, eb = g * epg;
    const int tid = threadIdx.x, lane = tid & 31, wid = tid >> 5;
    const int ei64 = g_flags[0], et64 = g_flags[1];

    for (int i = tid; i < nb; i += blockDim.x) cnt[i] = 0;
    __syncthreads();

    for (int e = tid; e < epg; e += blockDim.x) {
        int dst = (int)ldidx(ei, (size_t)E + eb + e, ei64);
        int t   = (int)ldidx(et, (size_t)(eb + e), et64);
        int b = (dst - bn) * RELC + t;
        ebuck[e] = b;
        atomicAdd(&cnt[b], 1);
    }
    __syncthreads();

    const int C = (nb + blockDim.x - 1) / blockDim.x;
    int start = tid * C, end = start + C; if (end > nb) end = nb; if (start > nb) start = nb;
    int s = 0;
    for (int i = start; i < end; i++) s += cnt[i];
    int v = s;
#pragma unroll
    for (int d = 1; d < 32; d <<= 1) { int n = __shfl_up_sync(~0u, v, d); if (lane >= d) v += n; }
    if (lane == 31) ws[wid] = v;
    __syncthreads();
    if (wid == 0) {
        int w = (lane < 8) ? ws[lane] : 0;
#pragma unroll
        for (int d = 1; d < 8; d <<= 1) { int n = __shfl_up_sync(~0u, w, d); if (lane >= d) w += n; }
        if (lane < 8) ws[lane] = w;
    }
    __syncthreads();
    int run = v - s + (wid ? ws[wid - 1] : 0);
    for (int i = start; i < end; i++) { offs[i] = run; cursor[i] = run; run += cnt[i]; }
    __syncthreads();

    for (int e = tid; e < epg; e += blockDim.x) {
        int src = (int)ldidx(ei, (size_t)(eb + e), ei64);
        int pos = atomicAdd(&cursor[ebuck[e]], 1);
        g_esrc[eb + pos] = src;
    }
    for (int i = tid; i < nb; i += blockDim.x) {
        g_off[bn * RELC + i]  = eb + offs[i];
        g_cnt8[bn * RELC + i] = cnt[i];
    }
}

// ---------------------------------------------------------------------------
// Gather: one warp per node. Computes per-(node,rel) bucket means of hin,
// splits fp16 hi/lo, packs k-pairs, writes both planes of g_pk. Also packs the
// root block (copy of hin row) at pairs 512..575. useH selects g_h input.
// ---------------------------------------------------------------------------
__global__ void __launch_bounds__(256)
gather_kernel(const float* __restrict__ xext, int useH, int n_nodes) {
    const float* __restrict__ hin = useH ? (const float*)g_h : xext;
    const int wid = threadIdx.x >> 5, lane = threadIdx.x & 31;
    const int n = blockIdx.x * 8 + wid;
    if (n >= n_nodes) return;
    u32* hi = &g_pk[(size_t)n * NPAIR];
    u32* lo = &g_pk[PLANE + (size_t)n * NPAIR];
#pragma unroll
    for (int r = 0; r < RELC; r++) {
        int b = n * RELC + r;
        int o0 = g_off[b], cn = g_cnt8[b];
        float4 acc = make_float4(0.f, 0.f, 0.f, 0.f);
        for (int i = 0; i < cn; i++) {
            int src = g_esrc[o0 + i];
            float4 hv = *reinterpret_cast<const float4*>(&hin[(size_t)src * EMBC + lane * 4]);
            acc.x += hv.x; acc.y += hv.y; acc.z += hv.z; acc.w += hv.w;
        }
        if (cn > 0) {
            float inv = 1.0f / (float)cn;
            acc.x *= inv; acc.y *= inv; acc.z *= inv; acc.w *= inv;
        }
        u32 h0, l0, h1, l1;
        pack_hl(acc.x, acc.y, h0, l0);
        pack_hl(acc.z, acc.w, h1, l1);
        *reinterpret_cast<uint2*>(&hi[r * 64 + lane * 2]) = make_uint2(h0, h1);
        *reinterpret_cast<uint2*>(&lo[r * 64 + lane * 2]) = make_uint2(l0, l1);
    }
    // root block: pairs 512..575
    {
        float4 hv = *reinterpret_cast<const float4*>(&hin[(size_t)n * EMBC + lane * 4]);
        u32 h0, l0, h1, l1;
        pack_hl(hv.x, hv.y, h0, l0);
        pack_hl(hv.z, hv.w, h1, l1);
        *reinterpret_cast<uint2*>(&hi[512 + lane * 2]) = make_uint2(h0, h1);
        *reinterpret_cast<uint2*>(&lo[512 + lane * 2]) = make_uint2(l0, l1);
    }
}

// ---------------------------------------------------------------------------
// GEMM via mma.sync m16n8k16 fp16 3-term split (ah*bh + ah*bl + al*bh):
// g_h[M,128] = relu?(A[M,1152] @ B + bias). A pre-split/packed in g_pk.
// CTA: 512 thr (16 warps, 4x4 m/n), out tile 128x128, K tiles of 32 (16 pairs),
// cp.async double-buffered. Inner loop = pure LDS.32 + HMMA.
// smem (u32): A[2 buf][2 plane][128][20] then B[2 buf][2 plane][16][136].
// A frag bank = 4*row+q (unique); B frag bank = 8*p+n (unique).
// ---------------------------------------------------------------------------
#define AS_U (2 * 128 * 20)   // 5120 u32 per A buffer (both planes)
#define BS_U (2 * 16 * 136)   // 4352 u32 per B buffer (both planes)
#define A_PL (128 * 20)       // 2560
#define B_PL (16 * 136)       // 2176
#define SMEM_GEMM ((2 * AS_U + 2 * BS_U) * 4)  // 75,776 B

__global__ void __launch_bounds__(512)
gemm_mma_kernel(const float* __restrict__ bias, int layer, int M, int do_relu) {
    extern __shared__ u32 smu[];
    const u32 sbase = smem_to_u32(smu);
    const int tid = threadIdx.x, lane = tid & 31, wid = tid >> 5;
    const int warp_m = wid >> 2, warp_n = wid & 3;
    const int m0 = blockIdx.x * 128;

    const u32* WtL = g_Wt + (size_t)layer * NKT * 2 * 2048;

    auto issue_tile = [&](int t, int b) {
        // A: 128 rows x 2 planes x 4 chunks = 1024 chunks (2 per thread)
#pragma unroll
        for (int j = 0; j < 2; j++) {
            int c = j * 512 + tid;
            int row = c >> 3, sub = c & 7;
            int plane = sub >> 2, ch = sub & 3;
            u32 dst = sbase + (u32)(b * AS_U + plane * A_PL + row * 20 + ch * 4) * 4;
            cp16(dst, &g_pk[(size_t)plane * PLANE + (size_t)(m0 + row) * NPAIR + t * 16 + ch * 4]);
        }
        // B: 2 planes x 16 p x 32 chunks = 1024 chunks (2 per thread)
        const u32* wb = WtL + (size_t)t * 2 * 2048;
#pragma unroll
        for (int j = 0; j < 2; j++) {
            int c = j * 512 + tid;
            int plane = c >> 9, rem = c & 511;
            int p = rem >> 5, ch = rem & 31;
            u32 dst = sbase + (u32)(2 * AS_U + b * BS_U + plane * B_PL + p * 136 + ch * 4) * 4;
            cp16(dst, wb + (size_t)plane * 2048 + p * 128 + ch * 4);
        }
    };

    float acc[2][4][4];
#pragma unroll
    for (int i = 0; i < 2; i++)
#pragma unroll
        for (int j = 0; j < 4; j++)
#pragma unroll
            for (int c = 0; c < 4; c++) acc[i][j][c] = 0.0f;

    issue_tile(0, 0);
    CP_COMMIT();

    const int q = lane & 3, gcol = lane >> 2;
    for (int t = 0; t < NKT; t++) {
        const int b = t & 1;
        if (t + 1 < NKT) { issue_tile(t + 1, (t + 1) & 1); CP_COMMIT(); CP_WAIT(1); }
        else { CP_WAIT(0); }
        __syncthreads();

        const u32* Ah = smu + b * AS_U;
        const u32* Al = Ah + A_PL;
        const u32* Bh = smu + 2 * AS_U + b * BS_U;
        const u32* Bl = Bh + B_PL;

#pragma unroll
        for (int s = 0; s < 2; s++) {
            const int pb = s * 8 + q;
            u32 ah[2][4], al[2][4];
#pragma unroll
            for (int mt = 0; mt < 2; mt++) {
                int rbase = (warp_m * 32 + mt * 16 + gcol) * 20 + pb;
                ah[mt][0] = Ah[rbase];
                ah[mt][1] = Ah[rbase + 8 * 20];
                ah[mt][2] = Ah[rbase + 4];
                ah[mt][3] = Ah[rbase + 8 * 20 + 4];
                al[mt][0] = Al[rbase];
                al[mt][1] = Al[rbase + 8 * 20];
                al[mt][2] = Al[rbase + 4];
                al[mt][3] = Al[rbase + 8 * 20 + 4];
            }
            u32 bh[4][2], bl[4][2];
#pragma unroll
            for (int nt = 0; nt < 4; nt++) {
                int col = warp_n * 32 + nt * 8 + gcol;
                int bidx = pb * 136 + col;
                bh[nt][0] = Bh[bidx];
                bh[nt][1] = Bh[bidx + 4 * 136];
                bl[nt][0] = Bl[bidx];
                bl[nt][1] = Bl[bidx + 4 * 136];
            }
#pragma unroll
            for (int mt = 0; mt < 2; mt++)
#pragma unroll
                for (int nt = 0; nt < 4; nt++) {
                    float* c = acc[mt][nt];
                    mma_f16(c[0], c[1], c[2], c[3],
                            ah[mt][0], ah[mt][1], ah[mt][2], ah[mt][3], bh[nt][0], bh[nt][1]);
                    mma_f16(c[0], c[1], c[2], c[3],
                            ah[mt][0], ah[mt][1], ah[mt][2], ah[mt][3], bl[nt][0], bl[nt][1]);
                    mma_f16(c[0], c[1], c[2], c[3],
                            al[mt][0], al[mt][1], al[mt][2], al[mt][3], bh[nt][0], bh[nt][1]);
                }
        }
        __syncthreads();
    }

    // epilogue: bias (+relu) -> g_h
#pragma unroll
    for (int mt = 0; mt < 2; mt++) {
        int row0 = m0 + warp_m * 32 + mt * 16 + gcol;
#pragma unroll
        for (int nt = 0; nt < 4; nt++) {
            int col = warp_n * 32 + nt * 8 + 2 * q;
            float bx = bias[col], by = bias[col + 1];
            float* c = acc[mt][nt];
            float2 v0 = make_float2(c[0] + bx, c[1] + by);
            float2 v1 = make_float2(c[2] + bx, c[3] + by);
            if (do_relu) {
                v0.x = fmaxf(v0.x, 0.f); v0.y = fmaxf(v0.y, 0.f);
                v1.x = fmaxf(v1.x, 0.f); v1.y = fmaxf(v1.y, 0.f);
            }
            if (row0 < M)
                *reinterpret_cast<float2*>(&g_h[(size_t)row0 * EMBC + col]) = v0;
            if (row0 + 8 < M)
                *reinterpret_cast<float2*>(&g_h[(size_t)(row0 + 8) * EMBC + col]) = v1;
        }
    }
}

// ---------------------------------------------------------------------------
// Score: logits[g, pos] = dot(node_emb[n], message_repr[g]); one warp per node
// ---------------------------------------------------------------------------
__global__ void score_kernel(float* __restrict__ outp, int n_nodes, int npg, int max_nodes) {
    const int wid = threadIdx.x >> 5, lane = threadIdx.x & 31;
    const int n = blockIdx.x * 8 + wid;
    if (n >= n_nodes) return;
    const int g = n / npg, pos = n - g * npg;
    float4 e = *reinterpret_cast<const float4*>(&g_h[(size_t)n * EMBC + lane * 4]);
    float4 m = *reinterpret_cast<const float4*>(&g_msg[(size_t)g * EMBC + lane * 4]);
    float p = e.x * m.x + e.y * m.y + e.z * m.z + e.w * m.w;
#pragma unroll
    for (int s = 16; s > 0; s >>= 1) p += __shfl_down_sync(~0u, p, s);
    if (lane == 0) outp[(size_t)g * max_nodes + pos] = p;
}

__global__ void pad_kernel(float* __restrict__ outp, int n_graphs, int npg, int max_nodes) {
    int i = blockIdx.x * blockDim.x + threadIdx.x;
    int per = max_nodes - npg;
    if (i >= n_graphs * per) return;
    int g = i / per, pos = npg + (i - g * per);
    outp[(size_t)g * max_nodes + pos] = -INFINITY;
}

// ---------------------------------------------------------------------------
// Launch.  Inputs: 0 message, 1 x, 2 edge_index, 3 edge_type, 4 batch,
// 5 max_nodes, 6 W1, 7 root1, 8 b1, 9 W2, 10 root2, 11 b2, 12 embed_table,
// 13 cont_w, 14 cont_b, 15 msg_w, 16 msg_b
// ---------------------------------------------------------------------------
extern "C" void kernel_launch(void* const* d_in, const int* in_sizes, int n_in,
                              void* d_out, int out_size) {
    const float* message = (const float*)d_in[0];
    const float* x       = (const float*)d_in[1];
    const void*  ei      = d_in[2];
    const void*  et      = d_in[3];
    const float* W1      = (const float*)d_in[6];
    const float* r1      = (const float*)d_in[7];
    const float* b1      = (const float*)d_in[8];
    const float* W2      = (const float*)d_in[9];
    const float* r2      = (const float*)d_in[10];
    const float* b2      = (const float*)d_in[11];
    const float* emb     = (const float*)d_in[12];
    const float* cw      = (const float*)d_in[13];
    const float* cbv     = (const float*)d_in[14];
    const float* mw      = (const float*)d_in[15];
    const float* mb      = (const float*)d_in[16];

    const int n_graphs  = in_sizes[0] / 2;
    const int n_nodes   = in_sizes[4];
    const int E         = in_sizes[3];
    const int vocab     = in_sizes[12] / EMBC;
    const int npg       = n_nodes / n_graphs;
    const int epg       = E / n_graphs;
    const int max_nodes = out_size / n_graphs;
    float* outp = (float*)d_out;

    const size_t csr_sm = ((size_t)npg * RELC * 3 + epg) * sizeof(int) + 64;
    cudaFuncSetAttribute(csr_kernel, cudaFuncAttributeMaxDynamicSharedMemorySize, (int)csr_sm);
    cudaFuncSetAttribute(gemm_mma_kernel, cudaFuncAttributeMaxDynamicSharedMemorySize, SMEM_GEMM);

    detect_kernel<<<1, 256>>>((const u32*)ei, (const u32*)et);
    repack_kernel<<<(2 * NPAIR * EMBC + 255) / 256, 256>>>(W1, r1, W2, r2);
    msg_kernel<<<n_graphs, EMBC>>>(message, emb, cw, cbv, mw, mb, vocab);
    csr_kernel<<<n_graphs, 256, csr_sm>>>(ei, et, npg, epg, E);

    const int MB = (n_nodes + 127) / 128;
    const int GB = (n_nodes + 7) / 8;

    // layer 1
    gather_kernel<<<GB, 256>>>(x, 0, n_nodes);
    gemm_mma_kernel<<<MB, 512, SMEM_GEMM>>>(b1, 0, n_nodes, 1);
    // layer 2
    gather_kernel<<<GB, 256>>>(x, 1, n_nodes);
    gemm_mma_kernel<<<MB, 512, SMEM_GEMM>>>(b2, 1, n_nodes, 0);

    score_kernel<<<GB, 256>>>(outp, n_nodes, npg, max_nodes);
    if (max_nodes > npg) {
        int pad = n_graphs * (max_nodes - npg);
        pad_kernel<<<(pad + 255) / 256, 256>>>(outp, n_graphs, npg, max_nodes);
    }
}